// round 11
// baseline (speedup 1.0000x reference)
#include <cuda_runtime.h>

#define GRID_BLOCKS 2048
#define BLOCK_THREADS 256

__device__ float g_sum = 0.0f;
__device__ unsigned int g_done_count = 0;

__global__ __launch_bounds__(BLOCK_THREADS, 8)
void mtnll_fused_kernel(const float* __restrict__ in0,
                        const float* __restrict__ in1,
                        const float* __restrict__ in2,
                        const float* __restrict__ cmap,
                        const int* __restrict__ t0,
                        const int* __restrict__ t1,
                        const int* __restrict__ t2,
                        float* __restrict__ out,
                        int n)
{
    float acc = 0.0f;

    // R3 mainloop: simple scalar grid-stride, 7 independent load streams.
    const int stride = gridDim.x * blockDim.x;
    for (int i = blockIdx.x * blockDim.x + threadIdx.x; i < n; i += stride) {
        const int   a = __ldg(&t0[i]);
        const int   b = __ldg(&t1[i]);
        const int   c = __ldg(&t2[i]);
        const float w = __ldg(&cmap[i]);
        const float p0 = __ldg(&in0[3 * i + a]);
        const float p1 = __ldg(&in1[3 * i + b]);
        const float p2 = __ldg(&in2[3 * i + c]);
        const float s = fmaf(0.5f, p1, fmaf(0.25f, p2, p0));
        acc = fmaf(-w, s, acc);
    }

    // intra-block reduction
    #pragma unroll
    for (int o = 16; o > 0; o >>= 1)
        acc += __shfl_xor_sync(0xffffffffu, acc, o);

    __shared__ float smem[BLOCK_THREADS / 32];
    const int warp = threadIdx.x >> 5;
    const int lane = threadIdx.x & 31;
    if (lane == 0) smem[warp] = acc;
    __syncthreads();

    // thread 0: one atomic into a single device scalar, then elect last block
    if (threadIdx.x == 0) {
        float bsum = 0.0f;
        #pragma unroll
        for (int w = 0; w < BLOCK_THREADS / 32; w++) bsum += smem[w];
        atomicAdd(&g_sum, bsum);
        __threadfence();
        unsigned int prev = atomicAdd(&g_done_count, 1u);
        if (prev == gridDim.x - 1) {
            // all blocks' adds are visible (their fence preceded their count bump)
            float total = *((volatile float*)&g_sum);
            out[0] = total * (1.0f / (float)n);
            g_sum = 0.0f;        // reset for next graph replay
            g_done_count = 0;
        }
    }
}

extern "C" void kernel_launch(void* const* d_in, const int* in_sizes, int n_in,
                              void* d_out, int out_size) {
    const float* in0  = (const float*)d_in[0];
    const float* in1  = (const float*)d_in[1];
    const float* in2  = (const float*)d_in[2];
    const float* cmap = (const float*)d_in[3];
    const int* t0     = (const int*)d_in[4];
    const int* t1     = (const int*)d_in[5];
    const int* t2     = (const int*)d_in[6];
    float* out = (float*)d_out;

    const int n = in_sizes[3];

    mtnll_fused_kernel<<<GRID_BLOCKS, BLOCK_THREADS>>>(
        in0, in1, in2, cmap, t0, t1, t2, out, n);
}